// round 3
// baseline (speedup 1.0000x reference)
#include <cuda_runtime.h>
#include <cuda_bf16.h>
#include <math.h>

#define NN 50000
#define EE 800000
#define DIN 64
#define DH 128
#define EPSF 1e-5f
#define SLOPEF 0.1f

// ---------------- scratch (device globals; no allocations) ----------------
__device__ __align__(16) float g_deg[NN];          // degree, then dinv in-place
__device__ int   g_rowstart[NN + 1];
__device__ int   g_cursor[NN];                     // counts, then write cursors
__device__ int   g_esrc[EE];
__device__ float g_enorm[EE];
__device__ __align__(16) float g_bufA[(size_t)NN * DH];
__device__ __align__(16) float g_bufB[(size_t)NN * DH];
__device__ __align__(16) float g_bufC[(size_t)NN * DH];
__device__ __align__(16) float g_res [(size_t)NN * DH];
__device__ float g_stats[4 * DH];                  // [sum0, sq0, sum1, sq1]

// ---------------- init: deg=1 (self loop), counts=0, stats=0 ----------------
__global__ __launch_bounds__(256) void k_init() {
    int i = blockIdx.x * blockDim.x + threadIdx.x;
    if (i < NN) { g_deg[i] = 1.0f; g_cursor[i] = 0; }
    if (i < 4 * DH) g_stats[i] = 0.0f;
}

// ---------------- edge pass 1: degree + histogram ----------------
__global__ __launch_bounds__(256) void k_edge1(const int* __restrict__ dst,
                                               const float* __restrict__ ew) {
    int e = blockIdx.x * blockDim.x + threadIdx.x;
    if (e >= EE) return;
    int d = dst[e];
    atomicAdd(&g_deg[d], ew[e]);
    atomicAdd(&g_cursor[d], 1);
}

// ---------------- single-block scan: rowstart, cursors, dinv ----------------
__global__ __launch_bounds__(1024) void k_scan() {
    __shared__ int part[1024];
    int t = threadIdx.x;
    const int chunk = (NN + 1023) / 1024;  // 49
    int start = t * chunk;
    int stop = start + chunk; if (stop > NN) stop = NN; if (start > NN) start = NN;
    int s = 0;
    for (int i = start; i < stop; ++i) s += g_cursor[i];
    part[t] = s;
    __syncthreads();
    // Hillis-Steele inclusive scan over 1024 partials
    for (int off = 1; off < 1024; off <<= 1) {
        int v = (t >= off) ? part[t - off] : 0;
        __syncthreads();
        part[t] += v;
        __syncthreads();
    }
    int run = (t == 0) ? 0 : part[t - 1];
    for (int i = start; i < stop; ++i) {
        int c = g_cursor[i];
        g_rowstart[i] = run;
        g_cursor[i] = run;
        run += c;
    }
    if (t == 1023) g_rowstart[NN] = run;   // == EE
    // dinv in-place (deg >= 1 always due to self loop)
    for (int i = t; i < NN; i += 1024) g_deg[i] = rsqrtf(g_deg[i]);
}

// ---------------- edge pass 2: scatter edges into CSR buckets ----------------
__global__ __launch_bounds__(256) void k_edge2(const int* __restrict__ src,
                                               const int* __restrict__ dst,
                                               const float* __restrict__ ew) {
    int e = blockIdx.x * blockDim.x + threadIdx.x;
    if (e >= EE) return;
    int s = src[e], d = dst[e];
    int p = atomicAdd(&g_cursor[d], 1);
    g_esrc[p] = s;
    g_enorm[p] = g_deg[s] * ew[e] * g_deg[d];
}

// ---------------- GEMM: C[N x 128] = A[N x K] @ B[K x 128] (+bias) ----------------
// 64-row x 128-col block tile, 256 threads, 8x4 micro-tile per thread.
// K processed in 64-wide chunks so static smem stays at exactly 48 KB.
template <int K>
__global__ __launch_bounds__(256) void k_gemm(const float* __restrict__ Aext, int Asel,
                                              const float* __restrict__ B,
                                              const float* __restrict__ bias, int Csel) {
    __shared__ float Bs[64 * DH];   // 32 KB
    __shared__ float As[64 * 64];   // 16 KB
    const float* __restrict__ A = (Asel == 0) ? Aext : g_bufA;
    float* C = (Csel == 0) ? g_bufA : ((Csel == 1) ? g_res : g_bufB);
    int t = threadIdx.x;
    int row0 = blockIdx.x * 64;
    int lane = t & 31, w = t >> 5;
    float4 acc[8];
#pragma unroll
    for (int j = 0; j < 8; j++) acc[j] = make_float4(0.f, 0.f, 0.f, 0.f);

    for (int kc = 0; kc < K / 64; kc++) {
        // cooperative load of B chunk [64 x 128]
        for (int i = t; i < 64 * DH / 4; i += 256)
            ((float4*)Bs)[i] = ((const float4*)(B + (size_t)kc * 64 * DH))[i];
        // cooperative load of A tile [64 rows x 64 k]
        for (int i = t; i < 64 * 64 / 4; i += 256) {
            int r = i >> 4, c = i & 15;
            int gr = row0 + r;
            float4 v = make_float4(0.f, 0.f, 0.f, 0.f);
            if (gr < NN) v = *(const float4*)(A + (size_t)gr * K + kc * 64 + c * 4);
            ((float4*)As)[i] = v;
        }
        __syncthreads();
        const float* Ar = As + w * 8 * 64;
#pragma unroll 4
        for (int k = 0; k < 64; k++) {
            float4 b = *(const float4*)(Bs + k * DH + lane * 4);
#pragma unroll
            for (int j = 0; j < 8; j++) {
                float a = Ar[j * 64 + k];   // warp-broadcast LDS
                acc[j].x = fmaf(a, b.x, acc[j].x);
                acc[j].y = fmaf(a, b.y, acc[j].y);
                acc[j].z = fmaf(a, b.z, acc[j].z);
                acc[j].w = fmaf(a, b.w, acc[j].w);
            }
        }
        __syncthreads();
    }
    float4 bv = make_float4(0.f, 0.f, 0.f, 0.f);
    if (bias) bv = ((const float4*)bias)[lane];
#pragma unroll
    for (int j = 0; j < 8; j++) {
        int gr = row0 + w * 8 + j;
        if (gr < NN) {
            float4 o = make_float4(acc[j].x + bv.x, acc[j].y + bv.y,
                                   acc[j].z + bv.z, acc[j].w + bv.w);
            *(float4*)(C + (size_t)gr * DH + lane * 4) = o;
        }
    }
}

// ---------------- aggregation: warp per node, CSR gather, no float atomics ----------------
__global__ __launch_bounds__(256) void k_agg(int sel, const float* __restrict__ bias) {
    const float* __restrict__ h = (sel == 0) ? g_bufA : g_bufB;
    float* __restrict__ o = (sel == 0) ? g_bufB : g_bufC;
    int node = (blockIdx.x * blockDim.x + threadIdx.x) >> 5;
    if (node >= NN) return;
    int lane = threadIdx.x & 31;
    const float4* __restrict__ h4 = (const float4*)h;

    float dv = g_deg[node];            // dinv
    float self = dv * dv;              // self-loop norm = 1/deg
    float4 bb = ((const float4*)bias)[lane];
    float4 hv = h4[(size_t)node * 32 + lane];
    float ax = fmaf(self, hv.x, bb.x);
    float ay = fmaf(self, hv.y, bb.y);
    float az = fmaf(self, hv.z, bb.z);
    float aw = fmaf(self, hv.w, bb.w);

    int e = g_rowstart[node];
    int end = g_rowstart[node + 1];
    for (; e + 4 <= end; e += 4) {
        int s0 = g_esrc[e + 0], s1 = g_esrc[e + 1], s2 = g_esrc[e + 2], s3 = g_esrc[e + 3];
        float w0 = g_enorm[e + 0], w1 = g_enorm[e + 1], w2 = g_enorm[e + 2], w3 = g_enorm[e + 3];
        float4 v0 = h4[(size_t)s0 * 32 + lane];
        float4 v1 = h4[(size_t)s1 * 32 + lane];
        float4 v2 = h4[(size_t)s2 * 32 + lane];
        float4 v3 = h4[(size_t)s3 * 32 + lane];
        ax = fmaf(w0, v0.x, ax); ay = fmaf(w0, v0.y, ay); az = fmaf(w0, v0.z, az); aw = fmaf(w0, v0.w, aw);
        ax = fmaf(w1, v1.x, ax); ay = fmaf(w1, v1.y, ay); az = fmaf(w1, v1.z, az); aw = fmaf(w1, v1.w, aw);
        ax = fmaf(w2, v2.x, ax); ay = fmaf(w2, v2.y, ay); az = fmaf(w2, v2.z, az); aw = fmaf(w2, v2.w, aw);
        ax = fmaf(w3, v3.x, ax); ay = fmaf(w3, v3.y, ay); az = fmaf(w3, v3.z, az); aw = fmaf(w3, v3.w, aw);
    }
    for (; e < end; ++e) {
        int s = g_esrc[e]; float ww = g_enorm[e];
        float4 v = h4[(size_t)s * 32 + lane];
        ax = fmaf(ww, v.x, ax); ay = fmaf(ww, v.y, ay);
        az = fmaf(ww, v.z, az); aw = fmaf(ww, v.w, aw);
    }
    ((float4*)o)[(size_t)node * 32 + lane] = make_float4(ax, ay, az, aw);
}

// ---------------- BN stats: per-feature sum & sumsq ----------------
__global__ __launch_bounds__(256) void k_stats(int bsel, int soff) {
    const float* __restrict__ buf = (bsel == 0) ? g_bufB : g_bufC;
    __shared__ float ssum[DH], ssq[DH];
    int t = threadIdx.x;
    if (t < DH) { ssum[t] = 0.f; ssq[t] = 0.f; }
    __syncthreads();
    int f = t & (DH - 1);
    int r = blockIdx.x * 2 + (t >> 7);
    float s = 0.f, q = 0.f;
    for (; r < NN; r += gridDim.x * 2) {
        float v = buf[(size_t)r * DH + f];
        s += v; q = fmaf(v, v, q);
    }
    atomicAdd(&ssum[f], s);
    atomicAdd(&ssq[f], q);
    __syncthreads();
    if (t < DH) {
        atomicAdd(&g_stats[soff + t], ssum[t]);
        atomicAdd(&g_stats[soff + DH + t], ssq[t]);
    }
}

// ---------------- layer-0 epilogue: BN + leaky + residual -> bufA ----------------
__global__ __launch_bounds__(256) void k_apply0(const float* __restrict__ gam,
                                                const float* __restrict__ bet) {
    __shared__ float sc[DH], sh[DH];
    int t = threadIdx.x;
    if (t < DH) {
        float mu = g_stats[t] * (1.0f / NN);
        float ex2 = g_stats[DH + t] * (1.0f / NN);
        float var = ex2 - mu * mu;
        float s = rsqrtf(var + EPSF) * gam[t];
        sc[t] = s;
        sh[t] = fmaf(-mu, s, bet[t]);
    }
    __syncthreads();
    int idx = blockIdx.x * blockDim.x + t;
    if (idx >= NN * 32) return;
    int f = (idx & 31) * 4;
    float4 v = ((const float4*)g_bufB)[idx];
    float4 r = ((const float4*)g_res)[idx];
    float x0 = fmaf(v.x, sc[f + 0], sh[f + 0]); x0 = (x0 >= 0.f) ? x0 : SLOPEF * x0; x0 += r.x;
    float x1 = fmaf(v.y, sc[f + 1], sh[f + 1]); x1 = (x1 >= 0.f) ? x1 : SLOPEF * x1; x1 += r.y;
    float x2 = fmaf(v.z, sc[f + 2], sh[f + 2]); x2 = (x2 >= 0.f) ? x2 : SLOPEF * x2; x2 += r.z;
    float x3 = fmaf(v.w, sc[f + 3], sh[f + 3]); x3 = (x3 >= 0.f) ? x3 : SLOPEF * x3; x3 += r.w;
    ((float4*)g_bufA)[idx] = make_float4(x0, x1, x2, x3);
}

// ---------------- final: BN + leaky + residual + row LayerNorm -> out ----------------
__global__ __launch_bounds__(256) void k_final(const float* __restrict__ gam,
                                               const float* __restrict__ bet,
                                               float* __restrict__ out) {
    __shared__ float sc[DH], sh[DH];
    int t = threadIdx.x;
    if (t < DH) {
        float mu = g_stats[2 * DH + t] * (1.0f / NN);
        float ex2 = g_stats[3 * DH + t] * (1.0f / NN);
        float var = ex2 - mu * mu;
        float s = rsqrtf(var + EPSF) * gam[t];
        sc[t] = s;
        sh[t] = fmaf(-mu, s, bet[t]);
    }
    __syncthreads();
    int node = blockIdx.x * 8 + (t >> 5);
    if (node >= NN) return;
    int lane = t & 31;
    float4 v = ((const float4*)g_bufC)[(size_t)node * 32 + lane];
    float4 r = ((const float4*)g_res)[(size_t)node * 32 + lane];
    int f = lane * 4;
    float x0 = fmaf(v.x, sc[f + 0], sh[f + 0]); x0 = (x0 >= 0.f) ? x0 : SLOPEF * x0; x0 += r.x;
    float x1 = fmaf(v.y, sc[f + 1], sh[f + 1]); x1 = (x1 >= 0.f) ? x1 : SLOPEF * x1; x1 += r.y;
    float x2 = fmaf(v.z, sc[f + 2], sh[f + 2]); x2 = (x2 >= 0.f) ? x2 : SLOPEF * x2; x2 += r.z;
    float x3 = fmaf(v.w, sc[f + 3], sh[f + 3]); x3 = (x3 >= 0.f) ? x3 : SLOPEF * x3; x3 += r.w;
    float s1 = x0 + x1 + x2 + x3;
    float s2 = x0 * x0 + x1 * x1 + x2 * x2 + x3 * x3;
#pragma unroll
    for (int off = 16; off; off >>= 1) {
        s1 += __shfl_xor_sync(0xFFFFFFFFu, s1, off);
        s2 += __shfl_xor_sync(0xFFFFFFFFu, s2, off);
    }
    float mu = s1 * (1.0f / DH);
    float var = s2 * (1.0f / DH) - mu * mu;
    float rs = rsqrtf(var + EPSF);
    ((float4*)out)[(size_t)node * 32 + lane] =
        make_float4((x0 - mu) * rs, (x1 - mu) * rs, (x2 - mu) * rs, (x3 - mu) * rs);
}

// ---------------- launch ----------------
extern "C" void kernel_launch(void* const* d_in, const int* in_sizes, int n_in,
                              void* d_out, int out_size) {
    const float* x    = (const float*)d_in[0];
    const int*   src  = (const int*)d_in[1];
    const int*   dst  = (const int*)d_in[2];
    const float* ew   = (const float*)d_in[3];
    const float* W0   = (const float*)d_in[4];
    const float* b0   = (const float*)d_in[5];
    const float* g0   = (const float*)d_in[6];
    const float* be0  = (const float*)d_in[7];
    const float* W1   = (const float*)d_in[8];
    const float* b1   = (const float*)d_in[9];
    const float* g1   = (const float*)d_in[10];
    const float* be1  = (const float*)d_in[11];
    const float* Wres = (const float*)d_in[12];
    const float* bres = (const float*)d_in[13];
    float* out = (float*)d_out;

    const int gridN = (NN + 255) / 256;
    const int gridE = (EE + 255) / 256;
    const int gridG = (NN + 63) / 64;        // gemm blocks (64 rows each)
    const int gridW = (NN + 7) / 8;          // warp-per-node kernels
    const int gridV = (NN * 32 + 255) / 256; // float4 elementwise

    // graph preprocessing (shared by both layers)
    k_init<<<gridN, 256>>>();
    k_edge1<<<gridE, 256>>>(dst, ew);
    k_scan<<<1, 1024>>>();
    k_edge2<<<gridE, 256>>>(src, dst, ew);

    // layer 0 transform + residual projection
    k_gemm<DIN><<<gridG, 256>>>(x, 0, W0, nullptr, 0);   // bufA = x @ W0
    k_gemm<DIN><<<gridG, 256>>>(x, 0, Wres, bres, 1);    // res  = x @ Wres + bres

    // layer 0 aggregate + BN + leaky + residual
    k_agg<<<gridW, 256>>>(0, b0);                        // bufB = Agg(bufA) + b0
    k_stats<<<256, 256>>>(0, 0);
    k_apply0<<<gridV, 256>>>(g0, be0);                   // bufA = act(bn(bufB)) + res

    // layer 1
    k_gemm<DH><<<gridG, 256>>>(nullptr, 1, W1, nullptr, 2); // bufB = bufA @ W1
    k_agg<<<gridW, 256>>>(1, b1);                           // bufC = Agg(bufB) + b1
    k_stats<<<256, 256>>>(1, 2 * DH);
    k_final<<<gridW, 256>>>(g1, be1, out);                  // out = LN(act(bn(bufC)) + res)
}